// round 2
// baseline (speedup 1.0000x reference)
#include <cuda_runtime.h>
#include <cuda_bf16.h>

#define NN 100000
#define EE 1600000
#define FIN 128
#define HF 128          // H*F
#define NH 8
#define FH 16
#define NC 40

// ---------------- scratch (static device globals; no allocation) ----------------
__device__ __align__(256) float d_h1[NN * HF];     // x @ W1
__device__ __align__(256) float d_g1[NN * HF];     // elu(agg1 + b1)
__device__ __align__(256) float d_h2[NN * NC];     // g1 @ W2
__device__ float d_as1[NN * NH];
__device__ float d_ad1[NN * NH];
__device__ float d_as2[NN];
__device__ float d_ad2[NN];
__device__ int   d_deg[NN];
__device__ int   d_rowoff[NN + 1];
__device__ int   d_cursor[NN];
__device__ int   d_csrsrc[EE];
__device__ int   d_is64;

// ---------------- edge index dtype detection (int32 vs int64) ----------------
__global__ void detect_kernel(const void* src) {
    const int* p = (const int*)src;
    int lane = threadIdx.x;           // 32 threads
    int v = p[2 * lane + 1];          // high word if int64, real value if int32
    unsigned b = __ballot_sync(0xFFFFFFFFu, v != 0);
    if (lane == 0) d_is64 = (b == 0) ? 1 : 0;
}

__device__ __forceinline__ int edge_at(const void* p, int i, int is64) {
    return is64 ? (int)((const long long*)p)[i] : ((const int*)p)[i];
}

// ---------------- CSR build ----------------
__global__ void zero_deg_kernel() {
    for (int i = blockIdx.x * blockDim.x + threadIdx.x; i < NN;
         i += gridDim.x * blockDim.x)
        d_deg[i] = 0;
}

__global__ void count_kernel(const void* dst) {
    int is64 = d_is64;
    for (int i = blockIdx.x * blockDim.x + threadIdx.x; i < EE;
         i += gridDim.x * blockDim.x) {
        int d = edge_at(dst, i, is64);
        atomicAdd(&d_deg[d], 1);
    }
}

__global__ void scan_kernel() {
    __shared__ int partial[1024];
    const int T = 1024;
    const int chunk = (NN + T - 1) / T;   // 98
    int t = threadIdx.x;
    int beg = t * chunk;
    int end = min(beg + chunk, NN);
    int s = 0;
    for (int i = beg; i < end; i++) s += d_deg[i];
    partial[t] = s;
    __syncthreads();
    for (int off = 1; off < T; off <<= 1) {
        int v = (t >= off) ? partial[t - off] : 0;
        __syncthreads();
        partial[t] += v;
        __syncthreads();
    }
    int run = (t == 0) ? 0 : partial[t - 1];
    for (int i = beg; i < end; i++) {
        d_rowoff[i] = run;
        d_cursor[i] = run;
        run += d_deg[i];
    }
    if (t == T - 1) d_rowoff[NN] = run;   // == EE
}

__global__ void fill_kernel(const void* src, const void* dst) {
    int is64 = d_is64;
    for (int i = blockIdx.x * blockDim.x + threadIdx.x; i < EE;
         i += gridDim.x * blockDim.x) {
        int s = edge_at(src, i, is64);
        int d = edge_at(dst, i, is64);
        int pos = atomicAdd(&d_cursor[d], 1);
        d_csrsrc[pos] = s;
    }
}

// ---------------- GEMM1: h1 = x @ W1  (N x 128 @ 128 x 128) ----------------
__global__ __launch_bounds__(256) void gemm1_kernel(const float* __restrict__ A,
                                                    const float* __restrict__ B) {
    __shared__ float As[16][128];   // [k][row]
    __shared__ float Bs[16][128];   // [k][col]
    int tid = threadIdx.x;          // 256
    int tr = (tid / 16) * 8;
    int tc = (tid % 16) * 8;
    int blockRow = blockIdx.x * 128;
    float acc[8][8];
#pragma unroll
    for (int i = 0; i < 8; i++)
#pragma unroll
        for (int j = 0; j < 8; j++) acc[i][j] = 0.f;

    int aIdx = tid * 8;
    int aRow = aIdx / 16, aCol = aIdx % 16;   // aCol in {0,8}
    int bIdx = tid * 8;
    int bRow = bIdx / 128, bCol = bIdx % 128;

    for (int k0 = 0; k0 < 128; k0 += 16) {
        int gRow = blockRow + aRow;
        float4 a0 = make_float4(0.f, 0.f, 0.f, 0.f);
        float4 a1 = make_float4(0.f, 0.f, 0.f, 0.f);
        if (gRow < NN) {
            a0 = *(const float4*)&A[gRow * 128 + k0 + aCol];
            a1 = *(const float4*)&A[gRow * 128 + k0 + aCol + 4];
        }
        As[aCol + 0][aRow] = a0.x; As[aCol + 1][aRow] = a0.y;
        As[aCol + 2][aRow] = a0.z; As[aCol + 3][aRow] = a0.w;
        As[aCol + 4][aRow] = a1.x; As[aCol + 5][aRow] = a1.y;
        As[aCol + 6][aRow] = a1.z; As[aCol + 7][aRow] = a1.w;

        float4 b0 = *(const float4*)&B[(k0 + bRow) * 128 + bCol];
        float4 b1 = *(const float4*)&B[(k0 + bRow) * 128 + bCol + 4];
        *(float4*)&Bs[bRow][bCol] = b0;
        *(float4*)&Bs[bRow][bCol + 4] = b1;
        __syncthreads();

#pragma unroll
        for (int k = 0; k < 16; k++) {
            float ra[8], rb[8];
#pragma unroll
            for (int i = 0; i < 8; i++) ra[i] = As[k][tr + i];
#pragma unroll
            for (int j = 0; j < 8; j++) rb[j] = Bs[k][tc + j];
#pragma unroll
            for (int i = 0; i < 8; i++)
#pragma unroll
                for (int j = 0; j < 8; j++) acc[i][j] += ra[i] * rb[j];
        }
        __syncthreads();
    }

#pragma unroll
    for (int i = 0; i < 8; i++) {
        int gRow = blockRow + tr + i;
        if (gRow < NN) {
            float4 o0 = make_float4(acc[i][0], acc[i][1], acc[i][2], acc[i][3]);
            float4 o1 = make_float4(acc[i][4], acc[i][5], acc[i][6], acc[i][7]);
            *(float4*)&d_h1[gRow * 128 + tc] = o0;
            *(float4*)&d_h1[gRow * 128 + tc + 4] = o1;
        }
    }
}

// ---------------- alpha1: per (node, head) dot with attention vectors ----------------
__global__ void alpha1_kernel(const float* __restrict__ asrc, const float* __restrict__ adst) {
    int tid = blockIdx.x * blockDim.x + threadIdx.x;
    if (tid >= NN * NH) return;
    int n = tid >> 3, hd = tid & 7;
    const float* hp = &d_h1[n * 128 + hd * 16];
    float s = 0.f, d = 0.f;
#pragma unroll
    for (int f = 0; f < 16; f++) {
        float v = hp[f];
        s += v * __ldg(&asrc[hd * 16 + f]);
        d += v * __ldg(&adst[hd * 16 + f]);
    }
    d_as1[tid] = s;
    d_ad1[tid] = d;
}

// ---------------- agg1: warp per dst node, 2-pass softmax, fused bias+ELU ----------------
__global__ __launch_bounds__(256) void agg1_kernel(const float* __restrict__ b1) {
    int warp = (blockIdx.x * blockDim.x + threadIdx.x) >> 5;
    int lane = threadIdx.x & 31;
    if (warp >= NN) return;
    int n = warp;
    int hd = lane >> 2;                  // 4 lanes per head; lane handles feats lane*4..+3
    float adv = d_ad1[n * 8 + hd];
    int beg = __shfl_sync(0xFFFFFFFFu, lane == 0 ? d_rowoff[n] : 0, 0);
    int end = __shfl_sync(0xFFFFFFFFu, lane == 1 ? d_rowoff[n + 1] : 0, 1);

    float m = -1e30f;
    for (int e = beg; e < end; e++) {
        int s = d_csrsrc[e];
        float v = d_as1[s * 8 + hd] + adv;
        v = v > 0.f ? v : 0.2f * v;
        m = fmaxf(m, v);
    }
    float psum = 0.f;
    float4 acc = make_float4(0.f, 0.f, 0.f, 0.f);
    for (int e = beg; e < end; e++) {
        int s = d_csrsrc[e];
        float v = d_as1[s * 8 + hd] + adv;
        v = v > 0.f ? v : 0.2f * v;
        float p = __expf(v - m);
        psum += p;
        float4 hv = *(const float4*)&d_h1[s * 128 + lane * 4];
        acc.x += p * hv.x; acc.y += p * hv.y;
        acc.z += p * hv.z; acc.w += p * hv.w;
    }
    float inv = psum > 0.f ? 1.f / psum : 0.f;
    float4 bb = *(const float4*)&b1[lane * 4];
    float4 o;
    o.x = acc.x * inv + bb.x;
    o.y = acc.y * inv + bb.y;
    o.z = acc.z * inv + bb.z;
    o.w = acc.w * inv + bb.w;
    // ELU
    o.x = o.x > 0.f ? o.x : __expf(o.x) - 1.f;
    o.y = o.y > 0.f ? o.y : __expf(o.y) - 1.f;
    o.z = o.z > 0.f ? o.z : __expf(o.z) - 1.f;
    o.w = o.w > 0.f ? o.w : __expf(o.w) - 1.f;
    *(float4*)&d_g1[n * 128 + lane * 4] = o;
}

// ---------------- GEMM2: h2 = g1 @ W2  (N x 128 @ 128 x 40) ----------------
__global__ void gemm2_kernel(const float* __restrict__ W2) {
    __shared__ float Gs[32][128];         // 16 KB
    __shared__ float W2s[128 * 40];       // 20 KB
    int tx = threadIdx.x;                 // 0..39 (col)
    int ty = threadIdx.y;                 // 0..7
    int tid = ty * 40 + tx;               // 0..319
    int blockRow = blockIdx.x * 32;

    for (int i = tid; i < 128 * 40; i += 320) W2s[i] = W2[i];
    for (int i = tid; i < 32 * 128; i += 320) {
        int r = i / 128, c = i % 128;
        int gr = blockRow + r;
        Gs[r][c] = (gr < NN) ? d_g1[gr * 128 + c] : 0.f;
    }
    __syncthreads();

    float acc[4] = {0.f, 0.f, 0.f, 0.f};
#pragma unroll 4
    for (int k = 0; k < 128; k++) {
        float w = W2s[k * 40 + tx];
#pragma unroll
        for (int i = 0; i < 4; i++) acc[i] += Gs[ty * 4 + i][k] * w;
    }
#pragma unroll
    for (int i = 0; i < 4; i++) {
        int gr = blockRow + ty * 4 + i;
        if (gr < NN) d_h2[gr * 40 + tx] = acc[i];
    }
}

// ---------------- alpha2: warp per node ----------------
__global__ void alpha2_kernel(const float* __restrict__ a_s, const float* __restrict__ a_d) {
    int warp = (blockIdx.x * blockDim.x + threadIdx.x) >> 5;
    int lane = threadIdx.x & 31;
    if (warp >= NN) return;
    const float* hp = &d_h2[warp * 40];
    float h0 = hp[lane];
    float vs = h0 * __ldg(&a_s[lane]);
    float vd = h0 * __ldg(&a_d[lane]);
    if (lane < 8) {
        float h1v = hp[32 + lane];
        vs += h1v * __ldg(&a_s[32 + lane]);
        vd += h1v * __ldg(&a_d[32 + lane]);
    }
#pragma unroll
    for (int off = 16; off; off >>= 1) {
        vs += __shfl_down_sync(0xFFFFFFFFu, vs, off);
        vd += __shfl_down_sync(0xFFFFFFFFu, vd, off);
    }
    if (lane == 0) { d_as2[warp] = vs; d_ad2[warp] = vd; }
}

// ---------------- agg2: warp per dst node, writes final output ----------------
__global__ __launch_bounds__(256) void agg2_kernel(const float* __restrict__ b2,
                                                   float* __restrict__ out) {
    int warp = (blockIdx.x * blockDim.x + threadIdx.x) >> 5;
    int lane = threadIdx.x & 31;
    if (warp >= NN) return;
    int n = warp;
    float adv = d_ad2[n];
    int beg = __shfl_sync(0xFFFFFFFFu, lane == 0 ? d_rowoff[n] : 0, 0);
    int end = __shfl_sync(0xFFFFFFFFu, lane == 1 ? d_rowoff[n + 1] : 0, 1);

    float m = -1e30f;
    for (int e = beg; e < end; e++) {
        int s = d_csrsrc[e];
        float v = d_as2[s] + adv;
        v = v > 0.f ? v : 0.2f * v;
        m = fmaxf(m, v);
    }
    float psum = 0.f, a0 = 0.f, a1 = 0.f;
    for (int e = beg; e < end; e++) {
        int s = d_csrsrc[e];
        float v = d_as2[s] + adv;
        v = v > 0.f ? v : 0.2f * v;
        float p = __expf(v - m);
        psum += p;
        a0 += p * d_h2[s * 40 + lane];
        if (lane < 8) a1 += p * d_h2[s * 40 + 32 + lane];
    }
    float inv = psum > 0.f ? 1.f / psum : 0.f;
    out[n * 40 + lane] = a0 * inv + __ldg(&b2[lane]);
    if (lane < 8) out[n * 40 + 32 + lane] = a1 * inv + __ldg(&b2[32 + lane]);
}

// ---------------- launch ----------------
extern "C" void kernel_launch(void* const* d_in, const int* in_sizes, int n_in,
                              void* d_out, int out_size) {
    const float* x    = (const float*)d_in[0];
    const void*  esrc = d_in[1];
    const void*  edst = d_in[2];
    const float* W1   = (const float*)d_in[3];
    const float* as1  = (const float*)d_in[4];
    const float* ad1  = (const float*)d_in[5];
    const float* b1   = (const float*)d_in[6];
    const float* W2   = (const float*)d_in[7];
    const float* as2  = (const float*)d_in[8];
    const float* ad2  = (const float*)d_in[9];
    const float* b2   = (const float*)d_in[10];
    float* out = (float*)d_out;

    // CSR build
    detect_kernel<<<1, 32>>>(esrc);
    zero_deg_kernel<<<256, 256>>>();
    count_kernel<<<512, 256>>>(edst);
    scan_kernel<<<1, 1024>>>();
    fill_kernel<<<512, 256>>>(esrc, edst);

    // Layer 1
    gemm1_kernel<<<(NN + 127) / 128, 256>>>(x, W1);
    alpha1_kernel<<<(NN * NH + 255) / 256, 256>>>(as1, ad1);
    agg1_kernel<<<(NN + 7) / 8, 256>>>(b1);

    // Layer 2
    gemm2_kernel<<<(NN + 31) / 32, dim3(40, 8)>>>(W2);
    alpha2_kernel<<<(NN * 32 + 255) / 256, 256>>>(as2, ad2);
    agg2_kernel<<<(NN + 7) / 8, 256>>>(b2, out);
}

// round 3
// speedup vs baseline: 1.4467x; 1.4467x over previous
#include <cuda_runtime.h>
#include <cuda_bf16.h>

#define NN 100000
#define EE 1600000
#define FIN 128
#define HF 128          // H*F
#define NH 8
#define FH 16
#define NC 40

#define SCAN_TILE 1024
#define NUM_TILES ((NN + SCAN_TILE - 1) / SCAN_TILE)   // 98

// ---------------- scratch (static device globals; no allocation) ----------------
__device__ __align__(256) float d_h1[NN * HF];     // x @ W1
__device__ __align__(256) float d_g1[NN * HF];     // elu(agg1 + b1)
__device__ __align__(256) float d_h2[NN * NC];     // g1 @ W2
__device__ float d_as1[NN * NH];
__device__ float d_ad1[NN * NH];
__device__ float d_as2[NN];
__device__ float d_ad2[NN];
__device__ int   d_deg[NN];
__device__ int   d_rowoff[NN + 1];
__device__ int   d_cursor[NN];
__device__ int   d_csrsrc[EE];
__device__ int   d_tilesum[NUM_TILES];
__device__ int   d_tileoff[NUM_TILES];
__device__ int   d_is64;

// ---------------- edge index dtype detection (int32 vs int64) ----------------
__global__ void detect_kernel(const void* src) {
    const int* p = (const int*)src;
    int lane = threadIdx.x;           // 32 threads
    int v = p[2 * lane + 1];          // high word if int64, real value if int32
    unsigned b = __ballot_sync(0xFFFFFFFFu, v != 0);
    if (lane == 0) d_is64 = (b == 0) ? 1 : 0;
}

__device__ __forceinline__ int edge_at(const void* p, int i, int is64) {
    return is64 ? (int)((const long long*)p)[i] : ((const int*)p)[i];
}

// ---------------- CSR build ----------------
__global__ void zero_deg_kernel() {
    for (int i = blockIdx.x * blockDim.x + threadIdx.x; i < NN;
         i += gridDim.x * blockDim.x)
        d_deg[i] = 0;
}

__global__ void count_kernel(const void* dst) {
    int is64 = d_is64;
    for (int i = blockIdx.x * blockDim.x + threadIdx.x; i < EE;
         i += gridDim.x * blockDim.x) {
        int d = edge_at(dst, i, is64);
        atomicAdd(&d_deg[d], 1);
    }
}

// --- scan phase 1: per-tile (1024 elems) sums, 256 threads/block ---
__global__ void tilesum_kernel() {
    __shared__ int ssum[8];
    int bid = blockIdx.x;
    int t = threadIdx.x;
    int base = bid * SCAN_TILE + t * 4;
    int s = 0;
#pragma unroll
    for (int i = 0; i < 4; i++) {
        int idx = base + i;
        if (idx < NN) s += d_deg[idx];
    }
#pragma unroll
    for (int off = 16; off; off >>= 1) s += __shfl_down_sync(0xFFFFFFFFu, s, off);
    if ((t & 31) == 0) ssum[t >> 5] = s;
    __syncthreads();
    if (t == 0) {
        int v = 0;
#pragma unroll
        for (int i = 0; i < 8; i++) v += ssum[i];
        d_tilesum[bid] = v;
    }
}

// --- scan phase 2: exclusive scan of tile sums (1 block, 128 threads) ---
__global__ void tilescan_kernel() {
    __shared__ int sh[128];
    int t = threadIdx.x;
    int v = (t < NUM_TILES) ? d_tilesum[t] : 0;
    sh[t] = v;
    __syncthreads();
    for (int off = 1; off < 128; off <<= 1) {
        int u = (t >= off) ? sh[t - off] : 0;
        __syncthreads();
        sh[t] += u;
        __syncthreads();
    }
    if (t < NUM_TILES) d_tileoff[t] = sh[t] - v;   // exclusive prefix
}

// --- scan phase 3: tile-local exclusive scan + global offset, write rowoff/cursor ---
__global__ void rowoff_kernel() {
    __shared__ int wsum[8], woff[8];
    int bid = blockIdx.x;
    int t = threadIdx.x;
    int lane = t & 31, w = t >> 5;
    int base = bid * SCAN_TILE + t * 4;
    int v[4];
    int ts = 0;
#pragma unroll
    for (int i = 0; i < 4; i++) {
        v[i] = (base + i < NN) ? d_deg[base + i] : 0;
        ts += v[i];
    }
    int incl = ts;
#pragma unroll
    for (int off = 1; off < 32; off <<= 1) {
        int u = __shfl_up_sync(0xFFFFFFFFu, incl, off);
        if (lane >= off) incl += u;
    }
    if (lane == 31) wsum[w] = incl;
    __syncthreads();
    if (t == 0) {
        int r = 0;
#pragma unroll
        for (int i = 0; i < 8; i++) { woff[i] = r; r += wsum[i]; }
    }
    __syncthreads();
    int run = d_tileoff[bid] + woff[w] + (incl - ts);
#pragma unroll
    for (int i = 0; i < 4; i++) {
        int idx = base + i;
        if (idx < NN) {
            d_rowoff[idx] = run;
            d_cursor[idx] = run;
            run += v[i];
        }
    }
    if (bid == 0 && t == 0) d_rowoff[NN] = EE;
}

__global__ void fill_kernel(const void* src, const void* dst) {
    int is64 = d_is64;
    for (int i = blockIdx.x * blockDim.x + threadIdx.x; i < EE;
         i += gridDim.x * blockDim.x) {
        int s = edge_at(src, i, is64);
        int d = edge_at(dst, i, is64);
        int pos = atomicAdd(&d_cursor[d], 1);
        d_csrsrc[pos] = s;
    }
}

// ---------------- GEMM1: h1 = x @ W1  (N x 128 @ 128 x 128) ----------------
__global__ __launch_bounds__(256) void gemm1_kernel(const float* __restrict__ A,
                                                    const float* __restrict__ B) {
    __shared__ float As[16][128];   // [k][row]
    __shared__ float Bs[16][128];   // [k][col]
    int tid = threadIdx.x;          // 256
    int tr = (tid / 16) * 8;
    int tc = (tid % 16) * 8;
    int blockRow = blockIdx.x * 128;
    float acc[8][8];
#pragma unroll
    for (int i = 0; i < 8; i++)
#pragma unroll
        for (int j = 0; j < 8; j++) acc[i][j] = 0.f;

    int aIdx = tid * 8;
    int aRow = aIdx / 16, aCol = aIdx % 16;   // aCol in {0,8}
    int bIdx = tid * 8;
    int bRow = bIdx / 128, bCol = bIdx % 128;

    for (int k0 = 0; k0 < 128; k0 += 16) {
        int gRow = blockRow + aRow;
        float4 a0 = make_float4(0.f, 0.f, 0.f, 0.f);
        float4 a1 = make_float4(0.f, 0.f, 0.f, 0.f);
        if (gRow < NN) {
            a0 = *(const float4*)&A[gRow * 128 + k0 + aCol];
            a1 = *(const float4*)&A[gRow * 128 + k0 + aCol + 4];
        }
        As[aCol + 0][aRow] = a0.x; As[aCol + 1][aRow] = a0.y;
        As[aCol + 2][aRow] = a0.z; As[aCol + 3][aRow] = a0.w;
        As[aCol + 4][aRow] = a1.x; As[aCol + 5][aRow] = a1.y;
        As[aCol + 6][aRow] = a1.z; As[aCol + 7][aRow] = a1.w;

        float4 b0 = *(const float4*)&B[(k0 + bRow) * 128 + bCol];
        float4 b1 = *(const float4*)&B[(k0 + bRow) * 128 + bCol + 4];
        *(float4*)&Bs[bRow][bCol] = b0;
        *(float4*)&Bs[bRow][bCol + 4] = b1;
        __syncthreads();

#pragma unroll
        for (int k = 0; k < 16; k++) {
            float ra[8], rb[8];
#pragma unroll
            for (int i = 0; i < 8; i++) ra[i] = As[k][tr + i];
#pragma unroll
            for (int j = 0; j < 8; j++) rb[j] = Bs[k][tc + j];
#pragma unroll
            for (int i = 0; i < 8; i++)
#pragma unroll
                for (int j = 0; j < 8; j++) acc[i][j] += ra[i] * rb[j];
        }
        __syncthreads();
    }

#pragma unroll
    for (int i = 0; i < 8; i++) {
        int gRow = blockRow + tr + i;
        if (gRow < NN) {
            float4 o0 = make_float4(acc[i][0], acc[i][1], acc[i][2], acc[i][3]);
            float4 o1 = make_float4(acc[i][4], acc[i][5], acc[i][6], acc[i][7]);
            *(float4*)&d_h1[gRow * 128 + tc] = o0;
            *(float4*)&d_h1[gRow * 128 + tc + 4] = o1;
        }
    }
}

// ---------------- alpha1: per (node, head) dot with attention vectors ----------------
__global__ void alpha1_kernel(const float* __restrict__ asrc, const float* __restrict__ adst) {
    int tid = blockIdx.x * blockDim.x + threadIdx.x;
    if (tid >= NN * NH) return;
    int n = tid >> 3, hd = tid & 7;
    const float4* hp = (const float4*)&d_h1[n * 128 + hd * 16];
    const float4* ap = (const float4*)&asrc[hd * 16];
    const float4* dp = (const float4*)&adst[hd * 16];
    float s = 0.f, d = 0.f;
#pragma unroll
    for (int f = 0; f < 4; f++) {
        float4 v = hp[f];
        float4 a = __ldg(&ap[f]);
        float4 b = __ldg(&dp[f]);
        s += v.x * a.x + v.y * a.y + v.z * a.z + v.w * a.w;
        d += v.x * b.x + v.y * b.y + v.z * b.z + v.w * b.w;
    }
    d_as1[tid] = s;
    d_ad1[tid] = d;
}

// ---- agg1: warp per dst node, single-pass ONLINE softmax, fused bias+ELU ----
__global__ __launch_bounds__(256) void agg1_kernel(const float* __restrict__ b1) {
    int warp = (blockIdx.x * blockDim.x + threadIdx.x) >> 5;
    int lane = threadIdx.x & 31;
    if (warp >= NN) return;
    int n = warp;
    int hd = lane >> 2;                  // 4 lanes per head; lane handles feats lane*4..+3
    float adv = d_ad1[n * 8 + hd];
    int beg = __shfl_sync(0xFFFFFFFFu, lane == 0 ? d_rowoff[n] : 0, 0);
    int end = __shfl_sync(0xFFFFFFFFu, lane == 1 ? d_rowoff[n + 1] : 0, 1);

    float m = -1e30f, psum = 0.f;
    float ax = 0.f, ay = 0.f, az = 0.f, aw = 0.f;
    for (int e = beg; e < end; e++) {
        int s = d_csrsrc[e];
        float v = d_as1[s * 8 + hd] + adv;
        v = v > 0.f ? v : 0.2f * v;
        float mn = fmaxf(m, v);
        float c = __expf(m - mn);        // 0 on first iter (m=-1e30)
        float p = __expf(v - mn);
        float4 hv = *(const float4*)&d_h1[s * 128 + lane * 4];
        psum = psum * c + p;
        ax = ax * c + p * hv.x;
        ay = ay * c + p * hv.y;
        az = az * c + p * hv.z;
        aw = aw * c + p * hv.w;
        m = mn;
    }
    float inv = psum > 0.f ? 1.f / psum : 0.f;
    float4 bb = *(const float4*)&b1[lane * 4];
    float4 o;
    o.x = ax * inv + bb.x;
    o.y = ay * inv + bb.y;
    o.z = az * inv + bb.z;
    o.w = aw * inv + bb.w;
    // ELU
    o.x = o.x > 0.f ? o.x : __expf(o.x) - 1.f;
    o.y = o.y > 0.f ? o.y : __expf(o.y) - 1.f;
    o.z = o.z > 0.f ? o.z : __expf(o.z) - 1.f;
    o.w = o.w > 0.f ? o.w : __expf(o.w) - 1.f;
    *(float4*)&d_g1[n * 128 + lane * 4] = o;
}

// ---------------- GEMM2: h2 = g1 @ W2  (N x 128 @ 128 x 40) ----------------
__global__ void gemm2_kernel(const float* __restrict__ W2) {
    __shared__ float Gs[32][128];         // 16 KB
    __shared__ float W2s[128 * 40];       // 20 KB
    int tx = threadIdx.x;                 // 0..39 (col)
    int ty = threadIdx.y;                 // 0..7
    int tid = ty * 40 + tx;               // 0..319
    int blockRow = blockIdx.x * 32;

    for (int i = tid; i < 128 * 40; i += 320) W2s[i] = W2[i];
    for (int i = tid; i < 32 * 128; i += 320) {
        int r = i / 128, c = i % 128;
        int gr = blockRow + r;
        Gs[r][c] = (gr < NN) ? d_g1[gr * 128 + c] : 0.f;
    }
    __syncthreads();

    float acc[4] = {0.f, 0.f, 0.f, 0.f};
#pragma unroll 4
    for (int k = 0; k < 128; k++) {
        float w = W2s[k * 40 + tx];
#pragma unroll
        for (int i = 0; i < 4; i++) acc[i] += Gs[ty * 4 + i][k] * w;
    }
#pragma unroll
    for (int i = 0; i < 4; i++) {
        int gr = blockRow + ty * 4 + i;
        if (gr < NN) d_h2[gr * 40 + tx] = acc[i];
    }
}

// ---------------- alpha2: warp per node ----------------
__global__ void alpha2_kernel(const float* __restrict__ a_s, const float* __restrict__ a_d) {
    int warp = (blockIdx.x * blockDim.x + threadIdx.x) >> 5;
    int lane = threadIdx.x & 31;
    if (warp >= NN) return;
    const float* hp = &d_h2[warp * 40];
    float h0 = hp[lane];
    float vs = h0 * __ldg(&a_s[lane]);
    float vd = h0 * __ldg(&a_d[lane]);
    if (lane < 8) {
        float h1v = hp[32 + lane];
        vs += h1v * __ldg(&a_s[32 + lane]);
        vd += h1v * __ldg(&a_d[32 + lane]);
    }
#pragma unroll
    for (int off = 16; off; off >>= 1) {
        vs += __shfl_down_sync(0xFFFFFFFFu, vs, off);
        vd += __shfl_down_sync(0xFFFFFFFFu, vd, off);
    }
    if (lane == 0) { d_as2[warp] = vs; d_ad2[warp] = vd; }
}

// ---- agg2: warp per dst node, single-pass online softmax, writes final output ----
__global__ __launch_bounds__(256) void agg2_kernel(const float* __restrict__ b2,
                                                   float* __restrict__ out) {
    int warp = (blockIdx.x * blockDim.x + threadIdx.x) >> 5;
    int lane = threadIdx.x & 31;
    if (warp >= NN) return;
    int n = warp;
    float adv = d_ad2[n];
    int beg = __shfl_sync(0xFFFFFFFFu, lane == 0 ? d_rowoff[n] : 0, 0);
    int end = __shfl_sync(0xFFFFFFFFu, lane == 1 ? d_rowoff[n + 1] : 0, 1);

    float m = -1e30f, psum = 0.f, a0 = 0.f, a1 = 0.f;
    for (int e = beg; e < end; e++) {
        int s = d_csrsrc[e];
        float v = d_as2[s] + adv;
        v = v > 0.f ? v : 0.2f * v;
        float mn = fmaxf(m, v);
        float c = __expf(m - mn);
        float p = __expf(v - mn);
        psum = psum * c + p;
        a0 = a0 * c + p * d_h2[s * 40 + lane];
        if (lane < 8) a1 = a1 * c + p * d_h2[s * 40 + 32 + lane];
        m = mn;
    }
    float inv = psum > 0.f ? 1.f / psum : 0.f;
    out[n * 40 + lane] = a0 * inv + __ldg(&b2[lane]);
    if (lane < 8) out[n * 40 + 32 + lane] = a1 * inv + __ldg(&b2[32 + lane]);
}

// ---------------- launch ----------------
extern "C" void kernel_launch(void* const* d_in, const int* in_sizes, int n_in,
                              void* d_out, int out_size) {
    const float* x    = (const float*)d_in[0];
    const void*  esrc = d_in[1];
    const void*  edst = d_in[2];
    const float* W1   = (const float*)d_in[3];
    const float* as1  = (const float*)d_in[4];
    const float* ad1  = (const float*)d_in[5];
    const float* b1   = (const float*)d_in[6];
    const float* W2   = (const float*)d_in[7];
    const float* as2  = (const float*)d_in[8];
    const float* ad2  = (const float*)d_in[9];
    const float* b2   = (const float*)d_in[10];
    float* out = (float*)d_out;

    // CSR build
    detect_kernel<<<1, 32>>>(esrc);
    zero_deg_kernel<<<256, 256>>>();
    count_kernel<<<512, 256>>>(edst);
    tilesum_kernel<<<NUM_TILES, 256>>>();
    tilescan_kernel<<<1, 128>>>();
    rowoff_kernel<<<NUM_TILES, 256>>>();
    fill_kernel<<<512, 256>>>(esrc, edst);

    // Layer 1
    gemm1_kernel<<<(NN + 127) / 128, 256>>>(x, W1);
    alpha1_kernel<<<(NN * NH + 255) / 256, 256>>>(as1, ad1);
    agg1_kernel<<<(NN + 7) / 8, 256>>>(b1);

    // Layer 2
    gemm2_kernel<<<(NN + 31) / 32, dim3(40, 8)>>>(W2);
    alpha2_kernel<<<(NN * 32 + 255) / 256, 256>>>(as2, ad2);
    agg2_kernel<<<(NN + 7) / 8, 256>>>(b2, out);
}